// round 4
// baseline (speedup 1.0000x reference)
#include <cuda_runtime.h>
#include <cstdint>
#include <climits>

#define MARGIN 0.2f
#define EPSV   1e-6f
#define MAX_IDS 65536

__device__ int   g_first[MAX_IDS];
__device__ int   g_second[MAX_IDS];
__device__ int   g_j0;          // first index with id != ids[0]
__device__ float g_total;
__device__ int   g_count;

// ---------------- kernel 1: init ----------------
__global__ void k_init() {
    int i = blockIdx.x * blockDim.x + threadIdx.x;
    if (i < MAX_IDS) {
        g_first[i]  = INT_MAX;
        g_second[i] = INT_MAX;
    }
    if (i == 0) {
        g_j0    = INT_MAX;
        g_total = 0.0f;
        g_count = 0;
    }
}

// ---------------- kernel 2: first occurrence + j0 ----------------
__global__ void k_pass1(const int* __restrict__ ids, int B) {
    int i = blockIdx.x * blockDim.x + threadIdx.x;
    if (i >= B) return;
    int id  = ids[i];
    int id0 = ids[0];           // L2/L1 broadcast, cheap
    atomicMin(&g_first[id & (MAX_IDS - 1)], i);
    if (id != id0) atomicMin(&g_j0, i);
}

// ---------------- kernel 3: second occurrence ----------------
__global__ void k_pass2(const int* __restrict__ ids, int B) {
    int i = blockIdx.x * blockDim.x + threadIdx.x;
    if (i >= B) return;
    int id = ids[i] & (MAX_IDS - 1);
    if (i != g_first[id]) atomicMin(&g_second[id], i);
}

// ---------------- kernel 4: main — one warp per row ----------------
__global__ void k_main(const float* __restrict__ P,
                       const int* __restrict__ ids,
                       int B, int D) {
    int gwarp = (blockIdx.x * blockDim.x + threadIdx.x) >> 5;
    int lane  = threadIdx.x & 31;
    int nwarps_blk = blockDim.x >> 5;
    int wid_blk = threadIdx.x >> 5;

    __shared__ float s_sum[32];
    __shared__ int   s_cnt[32];

    float per = 0.0f;
    int   cnt = 0;

    if (gwarp < B) {
        int i   = gwarp;
        int id  = ids[i] & (MAX_IDS - 1);
        int id0 = ids[0] & (MAX_IDS - 1);
        int f = g_first[id];
        int s = g_second[id];

        bool has_pos = (s != INT_MAX);
        int  pos_idx = (f != i) ? f : s;

        bool has_neg;
        int  neg_idx;
        if (id != id0) { neg_idx = 0;    has_neg = true; }
        else           { neg_idx = g_j0; has_neg = (g_j0 != INT_MAX); }

        if (has_pos && has_neg) {
            const float* pa = P + (size_t)i       * D;
            const float* pb = P + (size_t)pos_idx * D;
            const float* pc = P + (size_t)neg_idx * D;
            float dp = 0.0f, dn = 0.0f;
            for (int base = lane * 4; base < D; base += 128) {
                float4 a = *(const float4*)(pa + base);
                float4 b = *(const float4*)(pb + base);
                float4 c = *(const float4*)(pc + base);
                float t;
                t = a.x - b.x + EPSV; dp += t * t;
                t = a.y - b.y + EPSV; dp += t * t;
                t = a.z - b.z + EPSV; dp += t * t;
                t = a.w - b.w + EPSV; dp += t * t;
                t = a.x - c.x + EPSV; dn += t * t;
                t = a.y - c.y + EPSV; dn += t * t;
                t = a.z - c.z + EPSV; dn += t * t;
                t = a.w - c.w + EPSV; dn += t * t;
            }
            #pragma unroll
            for (int off = 16; off > 0; off >>= 1) {
                dp += __shfl_xor_sync(0xFFFFFFFFu, dp, off);
                dn += __shfl_xor_sync(0xFFFFFFFFu, dn, off);
            }
            if (lane == 0) {
                float v = sqrtf(dp) - sqrtf(dn) + MARGIN;
                per = (v > 0.0f) ? v : 0.0f;
                cnt = 1;
            }
        }
    }

    // block reduction: lane 0 of each warp deposits, warp 0 reduces
    if (lane == 0) { s_sum[wid_blk] = per; s_cnt[wid_blk] = cnt; }
    __syncthreads();
    if (wid_blk == 0) {
        float v = (lane < nwarps_blk) ? s_sum[lane] : 0.0f;
        int   c = (lane < nwarps_blk) ? s_cnt[lane] : 0;
        #pragma unroll
        for (int off = 16; off > 0; off >>= 1) {
            v += __shfl_xor_sync(0xFFFFFFFFu, v, off);
            c += __shfl_xor_sync(0xFFFFFFFFu, c, off);
        }
        if (lane == 0) {
            atomicAdd(&g_total, v);
            atomicAdd(&g_count, c);
        }
    }
}

// ---------------- kernel 5: finalize ----------------
__global__ void k_final(float* __restrict__ out) {
    int c = g_count;
    out[0] = g_total / (float)(c > 0 ? c : 1);
}

extern "C" void kernel_launch(void* const* d_in, const int* in_sizes, int n_in,
                              void* d_out, int out_size) {
    const float* P   = (const float*)d_in[0];
    const int*   ids = (const int*)d_in[1];
    float*       out = (float*)d_out;

    int B = in_sizes[1];
    int D = in_sizes[0] / B;

    k_init <<<(MAX_IDS + 255) / 256, 256>>>();
    k_pass1<<<(B + 255) / 256, 256>>>(ids, B);
    k_pass2<<<(B + 255) / 256, 256>>>(ids, B);

    int threads = 256;                       // 8 warps per block
    int rows_per_blk = threads / 32;
    int blocks = (B + rows_per_blk - 1) / rows_per_blk;
    k_main<<<blocks, threads>>>(P, ids, B, D);

    k_final<<<1, 1>>>(out);
}